// round 5
// baseline (speedup 1.0000x reference)
#include <cuda_runtime.h>
#include <math.h>

#define NN 100000
#define EE 1200000
#define CC 64
#define HH 64
#define OUTC 10
#define GG 128
#define LL 3
#define EPSBN 1e-5f

// ---------------- scratch (device globals) ----------------
__device__ float g_h [NN * HH];    // node features h
__device__ float g_aw[NN * HH];    // aggregated+BN'd features (GEMM input)
__device__ int   g_outdeg[NN];
__device__ int   g_indeg [NN];
__device__ int   g_rowptr[NN + 1];
__device__ int   g_cur   [NN];
__device__ int   g_col   [EE];
__device__ float g_dis   [NN];
__device__ int   g_bsum  [128];
__device__ int   g_boff  [128];
__device__ float g_stat_s[4 * 64]; // per-layer column-sum slots
__device__ float g_stat_q[4 * 64]; // per-layer column-sumsq slots
__device__ float g_hg    [GG * HH];

// ---------------- setup: degrees, stats zero, CSR ----------------
__global__ void k_zero_deg() {
    int i = blockIdx.x * blockDim.x + threadIdx.x;
    if (i < NN) { g_outdeg[i] = 0; g_indeg[i] = 0; }
    if (i < 256) { g_stat_s[i] = 0.f; g_stat_q[i] = 0.f; }
    if (i < GG * HH) g_hg[i] = 0.f;
}

__global__ void k_hist(const int* __restrict__ src, const int* __restrict__ dst) {
    int e = blockIdx.x * blockDim.x + threadIdx.x;
    if (e < EE) {
        atomicAdd(&g_indeg[dst[e]], 1);
        atomicAdd(&g_outdeg[src[e]], 1);
    }
}

__global__ void k_scan1() {
    __shared__ int sb[1024];
    int t = threadIdx.x;
    int i = blockIdx.x * 1024 + t;
    int v = (i < NN) ? g_indeg[i] : 0;
    sb[t] = v;
    __syncthreads();
    for (int off = 1; off < 1024; off <<= 1) {
        int x = (t >= off) ? sb[t - off] : 0;
        __syncthreads();
        sb[t] += x;
        __syncthreads();
    }
    if (i < NN) g_rowptr[i] = sb[t] - v;
    if (t == 1023) g_bsum[blockIdx.x] = sb[1023];
}

// parallel scan of the (<=128) block sums, one 128-thread block
__global__ void k_scan2(int nb) {
    __shared__ int sb[128];
    int t = threadIdx.x;
    int v = (t < nb) ? g_bsum[t] : 0;
    sb[t] = v;
    __syncthreads();
    for (int off = 1; off < 128; off <<= 1) {
        int x = (t >= off) ? sb[t - off] : 0;
        __syncthreads();
        sb[t] += x;
        __syncthreads();
    }
    g_boff[t] = sb[t] - v;          // exclusive
    if (t == 127) g_rowptr[NN] = sb[127];
}

__global__ void k_scan3() {
    int i = blockIdx.x * 1024 + threadIdx.x;
    if (i < NN) {
        int v = g_rowptr[i] + g_boff[blockIdx.x];
        g_rowptr[i] = v;
        g_cur[i] = v;
        g_dis[i] = rsqrtf((float)g_outdeg[i] + 1.0f);
    }
}

__global__ void k_fill(const int* __restrict__ src, const int* __restrict__ dst) {
    int e = blockIdx.x * blockDim.x + threadIdx.x;
    if (e < EE) {
        int d = dst[e];
        int p = atomicAdd(&g_cur[d], 1);
        g_col[p] = src[e];
    }
}

// ---------------- column stats for x (slot 0) ----------------
__global__ void k_colstats(const float* __restrict__ A) {
    __shared__ float rs[256], rq[256];
    int c  = threadIdx.x & 63;
    int rr = threadIdx.x >> 6;
    int rbeg = blockIdx.x * 512;
    int rend = rbeg + 512; if (rend > NN) rend = NN;
    float s = 0.f, q = 0.f;
    for (int r = rbeg + rr; r < rend; r += 4) {
        float v = A[(size_t)r * 64 + c];
        s += v; q += v * v;
    }
    rs[threadIdx.x] = s; rq[threadIdx.x] = q;
    __syncthreads();
    if (threadIdx.x < 64) {
        float S = rs[threadIdx.x] + rs[threadIdx.x + 64] + rs[threadIdx.x + 128] + rs[threadIdx.x + 192];
        float Q = rq[threadIdx.x] + rq[threadIdx.x + 64] + rq[threadIdx.x + 128] + rq[threadIdx.x + 192];
        atomicAdd(&g_stat_s[threadIdx.x], S);
        atomicAdd(&g_stat_q[threadIdx.x], Q);
    }
}

// ---------------- GEMM: out = relu(A' @ W + bias); A' optionally BN-affine of A ----------------
__global__ __launch_bounds__(256)
void k_gemm(const float* __restrict__ A, const float* __restrict__ W,
            const float* __restrict__ bias, float* __restrict__ out,
            int statSlot, int foldSlot,
            const float* __restrict__ gam, const float* __restrict__ bet) {
    __shared__ float sA[64 * 128];   // k-major (transposed) A-tile
    __shared__ float sW[64 * 64];
    __shared__ float s_s[64], s_t[64];
    int tid = threadIdx.x;
    int rowBase = blockIdx.x * 128;

    if (foldSlot >= 0) {
        if (tid < 64) {
            float invn = 1.0f / (float)NN;
            float mu  = g_stat_s[foldSlot * 64 + tid] * invn;
            float var = fmaxf(g_stat_q[foldSlot * 64 + tid] * invn - mu * mu, 0.f);
            float sc = rsqrtf(var + EPSBN) * gam[tid];
            s_s[tid] = sc;
            s_t[tid] = bet[tid] - mu * sc;
        }
        __syncthreads();
    }

    for (int i = tid * 4; i < 4096; i += 1024)
        *(float4*)(sW + i) = *(const float4*)(W + i);

    int lane = tid & 31, wid = tid >> 5;
    int k0 = wid * 8;
    float fs[8], ft[8];
    #pragma unroll
    for (int j = 0; j < 8; j++) {
        fs[j] = (foldSlot >= 0) ? s_s[k0 + j] : 1.f;
        ft[j] = (foldSlot >= 0) ? s_t[k0 + j] : 0.f;
    }
    #pragma unroll
    for (int rp = 0; rp < 4; rp++) {
        int r = rp * 32 + lane;
        int grow = rowBase + r;
        float4 v0 = make_float4(0.f, 0.f, 0.f, 0.f), v1 = v0;
        if (grow < NN) {
            const float4* p = (const float4*)(A + (size_t)grow * 64 + k0);
            v0 = p[0]; v1 = p[1];
        }
        sA[(k0 + 0) * 128 + r] = v0.x * fs[0] + ft[0];
        sA[(k0 + 1) * 128 + r] = v0.y * fs[1] + ft[1];
        sA[(k0 + 2) * 128 + r] = v0.z * fs[2] + ft[2];
        sA[(k0 + 3) * 128 + r] = v0.w * fs[3] + ft[3];
        sA[(k0 + 4) * 128 + r] = v1.x * fs[4] + ft[4];
        sA[(k0 + 5) * 128 + r] = v1.y * fs[5] + ft[5];
        sA[(k0 + 6) * 128 + r] = v1.z * fs[6] + ft[6];
        sA[(k0 + 7) * 128 + r] = v1.w * fs[7] + ft[7];
    }
    __syncthreads();

    int cx = (tid & 15) * 4;
    int ry = (tid >> 4) * 8;
    float acc[8][4];
    #pragma unroll
    for (int i = 0; i < 8; i++)
        #pragma unroll
        for (int j = 0; j < 4; j++) acc[i][j] = 0.f;

    #pragma unroll
    for (int k = 0; k < 64; k++) {
        float4 w  = *(const float4*)(sW + k * 64 + cx);
        float4 a0 = *(const float4*)(sA + k * 128 + ry);
        float4 a1 = *(const float4*)(sA + k * 128 + ry + 4);
        float a[8] = {a0.x, a0.y, a0.z, a0.w, a1.x, a1.y, a1.z, a1.w};
        #pragma unroll
        for (int i = 0; i < 8; i++) {
            acc[i][0] = fmaf(a[i], w.x, acc[i][0]);
            acc[i][1] = fmaf(a[i], w.y, acc[i][1]);
            acc[i][2] = fmaf(a[i], w.z, acc[i][2]);
            acc[i][3] = fmaf(a[i], w.w, acc[i][3]);
        }
    }

    float b0 = bias[cx], b1 = bias[cx + 1], b2 = bias[cx + 2], b3 = bias[cx + 3];
    float cs[4] = {0.f, 0.f, 0.f, 0.f}, cq[4] = {0.f, 0.f, 0.f, 0.f};
    #pragma unroll
    for (int i = 0; i < 8; i++) {
        int grow = rowBase + ry + i;
        if (grow < NN) {
            float4 o;
            o.x = fmaxf(acc[i][0] + b0, 0.f);
            o.y = fmaxf(acc[i][1] + b1, 0.f);
            o.z = fmaxf(acc[i][2] + b2, 0.f);
            o.w = fmaxf(acc[i][3] + b3, 0.f);
            *(float4*)(out + (size_t)grow * 64 + cx) = o;
            cs[0] += o.x; cq[0] += o.x * o.x;
            cs[1] += o.y; cq[1] += o.y * o.y;
            cs[2] += o.z; cq[2] += o.z * o.z;
            cs[3] += o.w; cq[3] += o.w * o.w;
        }
    }

    if (statSlot >= 0) {
        __syncthreads();
        float* sredS = sA;
        float* sredQ = sA + 512;
        #pragma unroll
        for (int j = 0; j < 4; j++) {
            cs[j] += __shfl_xor_sync(0xFFFFFFFFu, cs[j], 16);
            cq[j] += __shfl_xor_sync(0xFFFFFFFFu, cq[j], 16);
        }
        if (lane < 16) {
            #pragma unroll
            for (int j = 0; j < 4; j++) {
                sredS[wid * 64 + cx + j] = cs[j];
                sredQ[wid * 64 + cx + j] = cq[j];
            }
        }
        __syncthreads();
        if (tid < 64) {
            float S = 0.f, Q = 0.f;
            #pragma unroll
            for (int w = 0; w < 8; w++) { S += sredS[w * 64 + tid]; Q += sredQ[w * 64 + tid]; }
            atomicAdd(&g_stat_s[statSlot * 64 + tid], S);
            atomicAdd(&g_stat_q[statSlot * 64 + tid], Q);
        }
    }
}

// ---------------- aggregation (warp per node, cooperative edge metadata) ----------------
// Aout = sc ∘ (Σ_e w_e·h[src_e] + di²·h[i]) + (Σ w + di²)·sh
__global__ __launch_bounds__(256)
void k_agg(const float* __restrict__ Ain, float* __restrict__ Aout,
           int slot, const float* __restrict__ gam, const float* __restrict__ bet) {
    __shared__ float s_sc[64], s_sh[64];
    if (threadIdx.x < 64) {
        float invn = 1.0f / (float)NN;
        float mu  = g_stat_s[slot * 64 + threadIdx.x] * invn;
        float var = fmaxf(g_stat_q[slot * 64 + threadIdx.x] * invn - mu * mu, 0.f);
        float sc = rsqrtf(var + EPSBN) * gam[threadIdx.x];
        s_sc[threadIdx.x] = sc;
        s_sh[threadIdx.x] = bet[threadIdx.x] - mu * sc;
    }
    __syncthreads();

    int gtid = blockIdx.x * 256 + threadIdx.x;
    int i = gtid >> 5;
    int lane = gtid & 31;
    if (i >= NN) return;
    int c0 = lane * 2;
    float di = g_dis[i];
    int e0 = g_rowptr[i], end = g_rowptr[i + 1];
    int d = end - e0;
    int dc = d < 32 ? d : 32;

    // cooperative metadata: lane j owns edge e0+j
    int   sl = 0;
    float wl = 0.f;
    if (lane < dc) {
        sl = g_col[e0 + lane];
        wl = di * g_dis[sl];
    }
    // warp-total of weights (same on all lanes)
    float ws;
    {
        float wr = wl;
        #pragma unroll
        for (int off = 16; off > 0; off >>= 1)
            wr += __shfl_xor_sync(0xFFFFFFFFu, wr, off);
        ws = wr;
    }

    float a0 = 0.f, a1 = 0.f;
    int j = 0;
    for (; j + 4 <= dc; j += 4) {
        int   s0 = __shfl_sync(0xFFFFFFFFu, sl, j);
        int   s1 = __shfl_sync(0xFFFFFFFFu, sl, j + 1);
        int   s2 = __shfl_sync(0xFFFFFFFFu, sl, j + 2);
        int   s3 = __shfl_sync(0xFFFFFFFFu, sl, j + 3);
        float w0 = __shfl_sync(0xFFFFFFFFu, wl, j);
        float w1 = __shfl_sync(0xFFFFFFFFu, wl, j + 1);
        float w2 = __shfl_sync(0xFFFFFFFFu, wl, j + 2);
        float w3 = __shfl_sync(0xFFFFFFFFu, wl, j + 3);
        float2 v0 = *(const float2*)&Ain[(size_t)s0 * 64 + c0];
        float2 v1 = *(const float2*)&Ain[(size_t)s1 * 64 + c0];
        float2 v2 = *(const float2*)&Ain[(size_t)s2 * 64 + c0];
        float2 v3 = *(const float2*)&Ain[(size_t)s3 * 64 + c0];
        a0 = fmaf(w0, v0.x, a0); a1 = fmaf(w0, v0.y, a1);
        a0 = fmaf(w1, v1.x, a0); a1 = fmaf(w1, v1.y, a1);
        a0 = fmaf(w2, v2.x, a0); a1 = fmaf(w2, v2.y, a1);
        a0 = fmaf(w3, v3.x, a0); a1 = fmaf(w3, v3.y, a1);
    }
    for (; j < dc; j++) {
        int   s = __shfl_sync(0xFFFFFFFFu, sl, j);
        float w = __shfl_sync(0xFFFFFFFFu, wl, j);
        float2 v = *(const float2*)&Ain[(size_t)s * 64 + c0];
        a0 = fmaf(w, v.x, a0);
        a1 = fmaf(w, v.y, a1);
    }
    // rare tail: degree > 32
    for (int e = e0 + 32; e < end; e++) {
        int s = g_col[e];
        float w = di * g_dis[s];
        float2 v = *(const float2*)&Ain[(size_t)s * 64 + c0];
        a0 = fmaf(w, v.x, a0);
        a1 = fmaf(w, v.y, a1);
        ws += w;
    }
    {   // self loop
        float w = di * di;
        float2 v = *(const float2*)&Ain[(size_t)i * 64 + c0];
        a0 = fmaf(w, v.x, a0);
        a1 = fmaf(w, v.y, a1);
        ws += w;
    }
    float o0 = s_sc[c0]     * a0 + ws * s_sh[c0];
    float o1 = s_sc[c0 + 1] * a1 + ws * s_sh[c0 + 1];
    *(float2*)&Aout[(size_t)i * 64 + c0] = make_float2(o0, o1);
}

// ---------------- pooling ----------------
__global__ void k_pool(const int* __restrict__ batch, const float* __restrict__ hin) {
    int gtid = blockIdx.x * 256 + threadIdx.x;
    int warp = gtid >> 5;
    int lane = gtid & 31;
    int n0 = warp * 16;
    if (n0 >= NN) return;
    int nend = n0 + 16; if (nend > NN) nend = NN;
    int c0 = lane * 2;
    float a0 = 0.f, a1 = 0.f;
    int curg = batch[n0];
    for (int nd = n0; nd < nend; nd++) {
        int g = batch[nd];
        if (g != curg) {
            atomicAdd(&g_hg[curg * 64 + c0],     a0);
            atomicAdd(&g_hg[curg * 64 + c0 + 1], a1);
            a0 = 0.f; a1 = 0.f; curg = g;
        }
        float2 v = *(const float2*)&hin[(size_t)nd * 64 + c0];
        a0 += v.x; a1 += v.y;
    }
    atomicAdd(&g_hg[curg * 64 + c0],     a0);
    atomicAdd(&g_hg[curg * 64 + c0 + 1], a1);
}

// ---------------- final head ----------------
__global__ __launch_bounds__(256, 1)
void k_final(const float* __restrict__ bn1g, const float* __restrict__ bn1b,
             const float* __restrict__ Wfc,  const float* __restrict__ bfc,
             const float* __restrict__ bn2g, const float* __restrict__ bn2b,
             const float* __restrict__ Wcls, const float* __restrict__ bcls,
             float* __restrict__ out) {
    __shared__ float sA[128 * 65];
    __shared__ float red[256], red2[256];
    __shared__ float s_s[64], s_t[64];
    int tid = threadIdx.x;
    int c = tid & 63, rr = tid >> 6;

    for (int i = tid; i < 128 * 64; i += 256)
        sA[(i >> 6) * 65 + (i & 63)] = g_hg[i];
    __syncthreads();

    float s = 0.f, q = 0.f;
    for (int r = rr; r < 128; r += 4) {
        float v = sA[r * 65 + c];
        s += v; q += v * v;
    }
    red[tid] = s; red2[tid] = q;
    __syncthreads();
    if (tid < 64) {
        float S = red [tid] + red [tid + 64] + red [tid + 128] + red [tid + 192];
        float Q = red2[tid] + red2[tid + 64] + red2[tid + 128] + red2[tid + 192];
        float mu = S * (1.f / 128.f);
        float var = fmaxf(Q * (1.f / 128.f) - mu * mu, 0.f);
        float inv = rsqrtf(var + EPSBN);
        float sc = inv * bn1g[tid];
        s_s[tid] = sc;
        s_t[tid] = bn1b[tid] - mu * sc;
    }
    __syncthreads();
    for (int r = rr; r < 128; r += 4)
        sA[r * 65 + c] = sA[r * 65 + c] * s_s[c] + s_t[c];
    __syncthreads();

    float wreg[64];
    #pragma unroll
    for (int k = 0; k < 64; k++) wreg[k] = Wfc[k * 64 + c];
    float acc[32];
    for (int ri = 0; ri < 32; ri++) {
        int r = rr + ri * 4;
        float a = bfc[c];
        #pragma unroll
        for (int k = 0; k < 64; k++) a = fmaf(sA[r * 65 + k], wreg[k], a);
        acc[ri] = fmaxf(a, 0.f);
    }
    __syncthreads();
    for (int ri = 0; ri < 32; ri++) sA[(rr + ri * 4) * 65 + c] = acc[ri];
    __syncthreads();

    s = 0.f; q = 0.f;
    for (int r = rr; r < 128; r += 4) {
        float v = sA[r * 65 + c];
        s += v; q += v * v;
    }
    red[tid] = s; red2[tid] = q;
    __syncthreads();
    if (tid < 64) {
        float S = red [tid] + red [tid + 64] + red [tid + 128] + red [tid + 192];
        float Q = red2[tid] + red2[tid + 64] + red2[tid + 128] + red2[tid + 192];
        float mu = S * (1.f / 128.f);
        float var = fmaxf(Q * (1.f / 128.f) - mu * mu, 0.f);
        float inv = rsqrtf(var + EPSBN);
        float sc = inv * bn2g[tid];
        s_s[tid] = sc;
        s_t[tid] = bn2b[tid] - mu * sc;
    }
    __syncthreads();

    if (tid < 128) {
        int r = tid;
        float logits[10];
        #pragma unroll
        for (int j = 0; j < 10; j++) logits[j] = bcls[j];
        for (int k = 0; k < 64; k++) {
            float v = sA[r * 65 + k] * s_s[k] + s_t[k];
            #pragma unroll
            for (int j = 0; j < 10; j++)
                logits[j] = fmaf(v, Wcls[k * 10 + j], logits[j]);
        }
        float m = logits[0];
        #pragma unroll
        for (int j = 1; j < 10; j++) m = fmaxf(m, logits[j]);
        float se = 0.f;
        #pragma unroll
        for (int j = 0; j < 10; j++) se += expf(logits[j] - m);
        float lse = logf(se) + m;
        #pragma unroll
        for (int j = 0; j < 10; j++) out[r * 10 + j] = logits[j] - lse;
    }
}

// ---------------- host launch ----------------
extern "C" void kernel_launch(void* const* d_in, const int* in_sizes, int n_in,
                              void* d_out, int out_size) {
    const float* x         = (const float*)d_in[0];
    const int*   ei        = (const int*)  d_in[1];
    const int*   batch     = (const int*)  d_in[2];
    const float* bn_feat_g = (const float*)d_in[3];
    const float* bn_feat_b = (const float*)d_in[4];
    const float* W_feat    = (const float*)d_in[5];
    const float* b_feat    = (const float*)d_in[6];
    const float* conv_bn_g = (const float*)d_in[7];
    const float* conv_bn_b = (const float*)d_in[8];
    const float* conv_W    = (const float*)d_in[9];
    const float* conv_b    = (const float*)d_in[10];
    const float* bn_fc_g   = (const float*)d_in[11];
    const float* bn_fc_b   = (const float*)d_in[12];
    const float* W_fc      = (const float*)d_in[13];
    const float* b_fc      = (const float*)d_in[14];
    const float* bn_hid_g  = (const float*)d_in[15];
    const float* bn_hid_b  = (const float*)d_in[16];
    const float* W_cls     = (const float*)d_in[17];
    const float* b_cls     = (const float*)d_in[18];
    float* out = (float*)d_out;

    void *ph_v, *paw_v;
    cudaGetSymbolAddress(&ph_v,  g_h);
    cudaGetSymbolAddress(&paw_v, g_aw);
    float* ph  = (float*)ph_v;
    float* paw = (float*)paw_v;

    const int* src = ei;
    const int* dst = ei + EE;

    const int nbScan = (NN + 1023) / 1024;
    const int nbNode = (NN + 255) / 256;
    const int nbEdge = (EE + 255) / 256;
    const int nbStat = (NN + 511) / 512;
    const int nbGemm = (NN + 127) / 128;
    const int nbAgg  = (NN * 32 + 255) / 256;
    const int nbPool = (((NN + 15) / 16) * 32 + 255) / 256;

    // ---- CSR build ----
    k_zero_deg<<<nbNode, 256>>>();
    k_hist<<<nbEdge, 256>>>(src, dst);
    k_scan1<<<nbScan, 1024>>>();
    k_scan2<<<1, 128>>>(nbScan);
    k_scan3<<<nbScan, 1024>>>();
    k_fill<<<nbEdge, 256>>>(src, dst);

    // ---- feat layer: h = relu(BN(x) @ W_feat + b_feat); x stats slot0, h stats slot1 ----
    k_colstats<<<nbStat, 256>>>(x);
    k_gemm<<<nbGemm, 256>>>(x, W_feat, b_feat, ph, 1, 0, bn_feat_g, bn_feat_b);

    // ---- conv layers: agg (BN from slot l+1) -> GEMM (stats into slot l+2) ----
    for (int l = 0; l < LL; l++) {
        k_agg<<<nbAgg, 256>>>(ph, paw, l + 1, conv_bn_g + l * HH, conv_bn_b + l * HH);
        k_gemm<<<nbGemm, 256>>>(paw, conv_W + l * HH * HH, conv_b + l * HH, ph,
                                (l < LL - 1) ? (l + 2) : -1, -1,
                                (const float*)0, (const float*)0);
    }

    // ---- pool + head ----
    k_pool<<<nbPool, 256>>>(batch, ph);
    k_final<<<1, 256>>>(bn_fc_g, bn_fc_b, W_fc, b_fc,
                        bn_hid_g, bn_hid_b, W_cls, b_cls, out);
}

// round 6
// speedup vs baseline: 1.0794x; 1.0794x over previous
#include <cuda_runtime.h>
#include <math.h>

#define NN 100000
#define EE 1200000
#define CC 64
#define HH 64
#define OUTC 10
#define GG 128
#define LL 3
#define EPSBN 1e-5f

// ---------------- scratch (device globals) ----------------
__device__ float g_h [NN * HH];    // node features h
__device__ float g_aw[NN * HH];    // aggregated+BN'd features (GEMM input)
__device__ int   g_outdeg[NN];
__device__ int   g_indeg [NN];
__device__ int   g_rowptr[NN + 1];
__device__ int   g_cur   [NN];
__device__ int   g_col   [EE];
__device__ float g_dis   [NN];
__device__ int   g_bsum  [128];
__device__ int   g_boff  [128];
__device__ float g_stat_s[4 * 64]; // per-layer column-sum slots
__device__ float g_stat_q[4 * 64]; // per-layer column-sumsq slots
__device__ float g_hg    [GG * HH];

// ---------------- CSR chain ----------------
__global__ void k_zero_deg() {
    int i = blockIdx.x * blockDim.x + threadIdx.x;
    if (i < NN) { g_outdeg[i] = 0; g_indeg[i] = 0; }
}

__global__ void k_hist(const int* __restrict__ src, const int* __restrict__ dst) {
    int e = blockIdx.x * blockDim.x + threadIdx.x;
    if (e < EE) {
        atomicAdd(&g_indeg[dst[e]], 1);
        atomicAdd(&g_outdeg[src[e]], 1);
    }
}

__global__ void k_scan1() {
    __shared__ int sb[1024];
    int t = threadIdx.x;
    int i = blockIdx.x * 1024 + t;
    int v = (i < NN) ? g_indeg[i] : 0;
    sb[t] = v;
    __syncthreads();
    for (int off = 1; off < 1024; off <<= 1) {
        int x = (t >= off) ? sb[t - off] : 0;
        __syncthreads();
        sb[t] += x;
        __syncthreads();
    }
    if (i < NN) g_rowptr[i] = sb[t] - v;
    if (t == 1023) g_bsum[blockIdx.x] = sb[1023];
}

// parallel scan of the (<=128) block sums, one 128-thread block
__global__ void k_scan2(int nb) {
    __shared__ int sb[128];
    int t = threadIdx.x;
    int v = (t < nb) ? g_bsum[t] : 0;
    sb[t] = v;
    __syncthreads();
    for (int off = 1; off < 128; off <<= 1) {
        int x = (t >= off) ? sb[t - off] : 0;
        __syncthreads();
        sb[t] += x;
        __syncthreads();
    }
    g_boff[t] = sb[t] - v;          // exclusive
    if (t == 127) g_rowptr[NN] = sb[127];
}

__global__ void k_scan3() {
    int i = blockIdx.x * 1024 + threadIdx.x;
    if (i < NN) {
        int v = g_rowptr[i] + g_boff[blockIdx.x];
        g_rowptr[i] = v;
        g_cur[i] = v;
        g_dis[i] = rsqrtf((float)g_outdeg[i] + 1.0f);
    }
}

__global__ void k_fill(const int* __restrict__ src, const int* __restrict__ dst) {
    int e = blockIdx.x * blockDim.x + threadIdx.x;
    if (e < EE) {
        int d = dst[e];
        int p = atomicAdd(&g_cur[d], 1);
        g_col[p] = src[e];
    }
}

// ---------------- feature chain: zero stats+hg, column stats for x ----------------
__global__ void k_zero_stats() {
    int i = blockIdx.x * blockDim.x + threadIdx.x;
    if (i < 256) { g_stat_s[i] = 0.f; g_stat_q[i] = 0.f; }
    if (i < GG * HH) g_hg[i] = 0.f;
}

__global__ void k_colstats(const float* __restrict__ A) {
    __shared__ float rs[256], rq[256];
    int c  = threadIdx.x & 63;
    int rr = threadIdx.x >> 6;
    int rbeg = blockIdx.x * 512;
    int rend = rbeg + 512; if (rend > NN) rend = NN;
    float s = 0.f, q = 0.f;
    for (int r = rbeg + rr; r < rend; r += 4) {
        float v = A[(size_t)r * 64 + c];
        s += v; q += v * v;
    }
    rs[threadIdx.x] = s; rq[threadIdx.x] = q;
    __syncthreads();
    if (threadIdx.x < 64) {
        float S = rs[threadIdx.x] + rs[threadIdx.x + 64] + rs[threadIdx.x + 128] + rs[threadIdx.x + 192];
        float Q = rq[threadIdx.x] + rq[threadIdx.x + 64] + rq[threadIdx.x + 128] + rq[threadIdx.x + 192];
        atomicAdd(&g_stat_s[threadIdx.x], S);
        atomicAdd(&g_stat_q[threadIdx.x], Q);
    }
}

// ---------------- GEMM: out = relu(A' @ W + bias); A' optionally BN-affine of A ----------------
__global__ __launch_bounds__(256)
void k_gemm(const float* __restrict__ A, const float* __restrict__ W,
            const float* __restrict__ bias, float* __restrict__ out,
            int statSlot, int foldSlot,
            const float* __restrict__ gam, const float* __restrict__ bet) {
    __shared__ float sA[64 * 128];   // k-major (transposed) A-tile
    __shared__ float sW[64 * 64];
    __shared__ float s_s[64], s_t[64];
    int tid = threadIdx.x;
    int rowBase = blockIdx.x * 128;

    if (foldSlot >= 0) {
        if (tid < 64) {
            float invn = 1.0f / (float)NN;
            float mu  = g_stat_s[foldSlot * 64 + tid] * invn;
            float var = fmaxf(g_stat_q[foldSlot * 64 + tid] * invn - mu * mu, 0.f);
            float sc = rsqrtf(var + EPSBN) * gam[tid];
            s_s[tid] = sc;
            s_t[tid] = bet[tid] - mu * sc;
        }
        __syncthreads();
    }

    for (int i = tid * 4; i < 4096; i += 1024)
        *(float4*)(sW + i) = *(const float4*)(W + i);

    int lane = tid & 31, wid = tid >> 5;
    int k0 = wid * 8;
    float fs[8], ft[8];
    #pragma unroll
    for (int j = 0; j < 8; j++) {
        fs[j] = (foldSlot >= 0) ? s_s[k0 + j] : 1.f;
        ft[j] = (foldSlot >= 0) ? s_t[k0 + j] : 0.f;
    }
    #pragma unroll
    for (int rp = 0; rp < 4; rp++) {
        int r = rp * 32 + lane;
        int grow = rowBase + r;
        float4 v0 = make_float4(0.f, 0.f, 0.f, 0.f), v1 = v0;
        if (grow < NN) {
            const float4* p = (const float4*)(A + (size_t)grow * 64 + k0);
            v0 = p[0]; v1 = p[1];
        }
        sA[(k0 + 0) * 128 + r] = v0.x * fs[0] + ft[0];
        sA[(k0 + 1) * 128 + r] = v0.y * fs[1] + ft[1];
        sA[(k0 + 2) * 128 + r] = v0.z * fs[2] + ft[2];
        sA[(k0 + 3) * 128 + r] = v0.w * fs[3] + ft[3];
        sA[(k0 + 4) * 128 + r] = v1.x * fs[4] + ft[4];
        sA[(k0 + 5) * 128 + r] = v1.y * fs[5] + ft[5];
        sA[(k0 + 6) * 128 + r] = v1.z * fs[6] + ft[6];
        sA[(k0 + 7) * 128 + r] = v1.w * fs[7] + ft[7];
    }
    __syncthreads();

    int cx = (tid & 15) * 4;
    int ry = (tid >> 4) * 8;
    float acc[8][4];
    #pragma unroll
    for (int i = 0; i < 8; i++)
        #pragma unroll
        for (int j = 0; j < 4; j++) acc[i][j] = 0.f;

    #pragma unroll
    for (int k = 0; k < 64; k++) {
        float4 w  = *(const float4*)(sW + k * 64 + cx);
        float4 a0 = *(const float4*)(sA + k * 128 + ry);
        float4 a1 = *(const float4*)(sA + k * 128 + ry + 4);
        float a[8] = {a0.x, a0.y, a0.z, a0.w, a1.x, a1.y, a1.z, a1.w};
        #pragma unroll
        for (int i = 0; i < 8; i++) {
            acc[i][0] = fmaf(a[i], w.x, acc[i][0]);
            acc[i][1] = fmaf(a[i], w.y, acc[i][1]);
            acc[i][2] = fmaf(a[i], w.z, acc[i][2]);
            acc[i][3] = fmaf(a[i], w.w, acc[i][3]);
        }
    }

    float b0 = bias[cx], b1 = bias[cx + 1], b2 = bias[cx + 2], b3 = bias[cx + 3];
    float cs[4] = {0.f, 0.f, 0.f, 0.f}, cq[4] = {0.f, 0.f, 0.f, 0.f};
    #pragma unroll
    for (int i = 0; i < 8; i++) {
        int grow = rowBase + ry + i;
        if (grow < NN) {
            float4 o;
            o.x = fmaxf(acc[i][0] + b0, 0.f);
            o.y = fmaxf(acc[i][1] + b1, 0.f);
            o.z = fmaxf(acc[i][2] + b2, 0.f);
            o.w = fmaxf(acc[i][3] + b3, 0.f);
            *(float4*)(out + (size_t)grow * 64 + cx) = o;
            cs[0] += o.x; cq[0] += o.x * o.x;
            cs[1] += o.y; cq[1] += o.y * o.y;
            cs[2] += o.z; cq[2] += o.z * o.z;
            cs[3] += o.w; cq[3] += o.w * o.w;
        }
    }

    if (statSlot >= 0) {
        __syncthreads();
        float* sredS = sA;
        float* sredQ = sA + 512;
        #pragma unroll
        for (int j = 0; j < 4; j++) {
            cs[j] += __shfl_xor_sync(0xFFFFFFFFu, cs[j], 16);
            cq[j] += __shfl_xor_sync(0xFFFFFFFFu, cq[j], 16);
        }
        if (lane < 16) {
            #pragma unroll
            for (int j = 0; j < 4; j++) {
                sredS[wid * 64 + cx + j] = cs[j];
                sredQ[wid * 64 + cx + j] = cq[j];
            }
        }
        __syncthreads();
        if (tid < 64) {
            float S = 0.f, Q = 0.f;
            #pragma unroll
            for (int w = 0; w < 8; w++) { S += sredS[w * 64 + tid]; Q += sredQ[w * 64 + tid]; }
            atomicAdd(&g_stat_s[statSlot * 64 + tid], S);
            atomicAdd(&g_stat_q[statSlot * 64 + tid], Q);
        }
    }
}

// ---------------- aggregation (warp per node; R4 proven body) ----------------
__global__ __launch_bounds__(256)
void k_agg(const float* __restrict__ Ain, float* __restrict__ Aout,
           int slot, const float* __restrict__ gam, const float* __restrict__ bet) {
    __shared__ float s_sc[64], s_sh[64];
    if (threadIdx.x < 64) {
        float invn = 1.0f / (float)NN;
        float mu  = g_stat_s[slot * 64 + threadIdx.x] * invn;
        float var = fmaxf(g_stat_q[slot * 64 + threadIdx.x] * invn - mu * mu, 0.f);
        float sc = rsqrtf(var + EPSBN) * gam[threadIdx.x];
        s_sc[threadIdx.x] = sc;
        s_sh[threadIdx.x] = bet[threadIdx.x] - mu * sc;
    }
    __syncthreads();

    int gtid = blockIdx.x * 256 + threadIdx.x;
    int i = gtid >> 5;
    int lane = gtid & 31;
    if (i >= NN) return;
    int c0 = lane * 2;
    float di = g_dis[i];
    int e = g_rowptr[i], end = g_rowptr[i + 1];
    float a0 = 0.f, a1 = 0.f, ws = 0.f;

    for (; e + 4 <= end; e += 4) {
        int s0 = g_col[e], s1 = g_col[e + 1], s2 = g_col[e + 2], s3 = g_col[e + 3];
        float w0 = g_dis[s0], w1 = g_dis[s1], w2 = g_dis[s2], w3 = g_dis[s3];
        float2 v0 = *(const float2*)&Ain[(size_t)s0 * 64 + c0];
        float2 v1 = *(const float2*)&Ain[(size_t)s1 * 64 + c0];
        float2 v2 = *(const float2*)&Ain[(size_t)s2 * 64 + c0];
        float2 v3 = *(const float2*)&Ain[(size_t)s3 * 64 + c0];
        w0 *= di; w1 *= di; w2 *= di; w3 *= di;
        a0 = fmaf(w0, v0.x, a0); a1 = fmaf(w0, v0.y, a1);
        a0 = fmaf(w1, v1.x, a0); a1 = fmaf(w1, v1.y, a1);
        a0 = fmaf(w2, v2.x, a0); a1 = fmaf(w2, v2.y, a1);
        a0 = fmaf(w3, v3.x, a0); a1 = fmaf(w3, v3.y, a1);
        ws += w0 + w1 + w2 + w3;
    }
    for (; e < end; e++) {
        int s = g_col[e];
        float w = di * g_dis[s];
        float2 v = *(const float2*)&Ain[(size_t)s * 64 + c0];
        a0 = fmaf(w, v.x, a0);
        a1 = fmaf(w, v.y, a1);
        ws += w;
    }
    {   // self loop
        float w = di * di;
        float2 v = *(const float2*)&Ain[(size_t)i * 64 + c0];
        a0 = fmaf(w, v.x, a0);
        a1 = fmaf(w, v.y, a1);
        ws += w;
    }
    float o0 = s_sc[c0]     * a0 + ws * s_sh[c0];
    float o1 = s_sc[c0 + 1] * a1 + ws * s_sh[c0 + 1];
    *(float2*)&Aout[(size_t)i * 64 + c0] = make_float2(o0, o1);
}

// ---------------- pooling ----------------
__global__ void k_pool(const int* __restrict__ batch, const float* __restrict__ hin) {
    int gtid = blockIdx.x * 256 + threadIdx.x;
    int warp = gtid >> 5;
    int lane = gtid & 31;
    int n0 = warp * 16;
    if (n0 >= NN) return;
    int nend = n0 + 16; if (nend > NN) nend = NN;
    int c0 = lane * 2;
    float a0 = 0.f, a1 = 0.f;
    int curg = batch[n0];
    for (int nd = n0; nd < nend; nd++) {
        int g = batch[nd];
        if (g != curg) {
            atomicAdd(&g_hg[curg * 64 + c0],     a0);
            atomicAdd(&g_hg[curg * 64 + c0 + 1], a1);
            a0 = 0.f; a1 = 0.f; curg = g;
        }
        float2 v = *(const float2*)&hin[(size_t)nd * 64 + c0];
        a0 += v.x; a1 += v.y;
    }
    atomicAdd(&g_hg[curg * 64 + c0],     a0);
    atomicAdd(&g_hg[curg * 64 + c0 + 1], a1);
}

// ---------------- final head ----------------
__global__ __launch_bounds__(256, 1)
void k_final(const float* __restrict__ bn1g, const float* __restrict__ bn1b,
             const float* __restrict__ Wfc,  const float* __restrict__ bfc,
             const float* __restrict__ bn2g, const float* __restrict__ bn2b,
             const float* __restrict__ Wcls, const float* __restrict__ bcls,
             float* __restrict__ out) {
    __shared__ float sA[128 * 65];
    __shared__ float red[256], red2[256];
    __shared__ float s_s[64], s_t[64];
    int tid = threadIdx.x;
    int c = tid & 63, rr = tid >> 6;

    for (int i = tid; i < 128 * 64; i += 256)
        sA[(i >> 6) * 65 + (i & 63)] = g_hg[i];
    __syncthreads();

    float s = 0.f, q = 0.f;
    for (int r = rr; r < 128; r += 4) {
        float v = sA[r * 65 + c];
        s += v; q += v * v;
    }
    red[tid] = s; red2[tid] = q;
    __syncthreads();
    if (tid < 64) {
        float S = red [tid] + red [tid + 64] + red [tid + 128] + red [tid + 192];
        float Q = red2[tid] + red2[tid + 64] + red2[tid + 128] + red2[tid + 192];
        float mu = S * (1.f / 128.f);
        float var = fmaxf(Q * (1.f / 128.f) - mu * mu, 0.f);
        float inv = rsqrtf(var + EPSBN);
        float sc = inv * bn1g[tid];
        s_s[tid] = sc;
        s_t[tid] = bn1b[tid] - mu * sc;
    }
    __syncthreads();
    for (int r = rr; r < 128; r += 4)
        sA[r * 65 + c] = sA[r * 65 + c] * s_s[c] + s_t[c];
    __syncthreads();

    float wreg[64];
    #pragma unroll
    for (int k = 0; k < 64; k++) wreg[k] = Wfc[k * 64 + c];
    float acc[32];
    for (int ri = 0; ri < 32; ri++) {
        int r = rr + ri * 4;
        float a = bfc[c];
        #pragma unroll
        for (int k = 0; k < 64; k++) a = fmaf(sA[r * 65 + k], wreg[k], a);
        acc[ri] = fmaxf(a, 0.f);
    }
    __syncthreads();
    for (int ri = 0; ri < 32; ri++) sA[(rr + ri * 4) * 65 + c] = acc[ri];
    __syncthreads();

    s = 0.f; q = 0.f;
    for (int r = rr; r < 128; r += 4) {
        float v = sA[r * 65 + c];
        s += v; q += v * v;
    }
    red[tid] = s; red2[tid] = q;
    __syncthreads();
    if (tid < 64) {
        float S = red [tid] + red [tid + 64] + red [tid + 128] + red [tid + 192];
        float Q = red2[tid] + red2[tid + 64] + red2[tid + 128] + red2[tid + 192];
        float mu = S * (1.f / 128.f);
        float var = fmaxf(Q * (1.f / 128.f) - mu * mu, 0.f);
        float inv = rsqrtf(var + EPSBN);
        float sc = inv * bn2g[tid];
        s_s[tid] = sc;
        s_t[tid] = bn2b[tid] - mu * sc;
    }
    __syncthreads();

    if (tid < 128) {
        int r = tid;
        float logits[10];
        #pragma unroll
        for (int j = 0; j < 10; j++) logits[j] = bcls[j];
        for (int k = 0; k < 64; k++) {
            float v = sA[r * 65 + k] * s_s[k] + s_t[k];
            #pragma unroll
            for (int j = 0; j < 10; j++)
                logits[j] = fmaf(v, Wcls[k * 10 + j], logits[j]);
        }
        float m = logits[0];
        #pragma unroll
        for (int j = 1; j < 10; j++) m = fmaxf(m, logits[j]);
        float se = 0.f;
        #pragma unroll
        for (int j = 0; j < 10; j++) se += expf(logits[j] - m);
        float lse = logf(se) + m;
        #pragma unroll
        for (int j = 0; j < 10; j++) out[r * 10 + j] = logits[j] - lse;
    }
}

// ---------------- host launch ----------------
extern "C" void kernel_launch(void* const* d_in, const int* in_sizes, int n_in,
                              void* d_out, int out_size) {
    const float* x         = (const float*)d_in[0];
    const int*   ei        = (const int*)  d_in[1];
    const int*   batch     = (const int*)  d_in[2];
    const float* bn_feat_g = (const float*)d_in[3];
    const float* bn_feat_b = (const float*)d_in[4];
    const float* W_feat    = (const float*)d_in[5];
    const float* b_feat    = (const float*)d_in[6];
    const float* conv_bn_g = (const float*)d_in[7];
    const float* conv_bn_b = (const float*)d_in[8];
    const float* conv_W    = (const float*)d_in[9];
    const float* conv_b    = (const float*)d_in[10];
    const float* bn_fc_g   = (const float*)d_in[11];
    const float* bn_fc_b   = (const float*)d_in[12];
    const float* W_fc      = (const float*)d_in[13];
    const float* b_fc      = (const float*)d_in[14];
    const float* bn_hid_g  = (const float*)d_in[15];
    const float* bn_hid_b  = (const float*)d_in[16];
    const float* W_cls     = (const float*)d_in[17];
    const float* b_cls     = (const float*)d_in[18];
    float* out = (float*)d_out;

    void *ph_v, *paw_v;
    cudaGetSymbolAddress(&ph_v,  g_h);
    cudaGetSymbolAddress(&paw_v, g_aw);
    float* ph  = (float*)ph_v;
    float* paw = (float*)paw_v;

    const int* src = ei;
    const int* dst = ei + EE;

    const int nbScan = (NN + 1023) / 1024;
    const int nbNode = (NN + 255) / 256;
    const int nbEdge = (EE + 255) / 256;
    const int nbStat = (NN + 511) / 512;
    const int nbGemm = (NN + 127) / 128;
    const int nbAgg  = (NN * 32 + 255) / 256;
    const int nbPool = (((NN + 15) / 16) * 32 + 255) / 256;

    // lazily created side stream + fork/join events (created outside capture on
    // the first correctness call; reused by the capture call — still only
    // kernel launches + event edges inside the captured graph)
    static cudaStream_t s_csr = 0;
    static cudaEvent_t  ev_fork = 0, ev_join = 0;
    if (!s_csr) {
        cudaStreamCreateWithFlags(&s_csr, cudaStreamNonBlocking);
        cudaEventCreateWithFlags(&ev_fork, cudaEventDisableTiming);
        cudaEventCreateWithFlags(&ev_join, cudaEventDisableTiming);
    }

    // ---- fork: CSR chain on s_csr, feature chain on stream 0 ----
    cudaEventRecord(ev_fork, 0);
    cudaStreamWaitEvent(s_csr, ev_fork, 0);

    k_zero_deg<<<nbNode, 256, 0, s_csr>>>();
    k_hist<<<nbEdge, 256, 0, s_csr>>>(src, dst);
    k_scan1<<<nbScan, 1024, 0, s_csr>>>();
    k_scan2<<<1, 128, 0, s_csr>>>(nbScan);
    k_scan3<<<nbScan, 1024, 0, s_csr>>>();
    k_fill<<<nbEdge, 256, 0, s_csr>>>(src, dst);
    cudaEventRecord(ev_join, s_csr);

    // feature chain (stream 0): zero stats, colstats(x), feat GEMM
    k_zero_stats<<<33, 256>>>();
    k_colstats<<<nbStat, 256>>>(x);
    k_gemm<<<nbGemm, 256>>>(x, W_feat, b_feat, ph, 1, 0, bn_feat_g, bn_feat_b);

    // ---- join before first aggregation ----
    cudaStreamWaitEvent(0, ev_join, 0);

    // ---- conv layers: agg (BN from slot l+1) -> GEMM (stats into slot l+2) ----
    for (int l = 0; l < LL; l++) {
        k_agg<<<nbAgg, 256>>>(ph, paw, l + 1, conv_bn_g + l * HH, conv_bn_b + l * HH);
        k_gemm<<<nbGemm, 256>>>(paw, conv_W + l * HH * HH, conv_b + l * HH, ph,
                                (l < LL - 1) ? (l + 2) : -1, -1,
                                (const float*)0, (const float*)0);
    }

    // ---- pool + head ----
    k_pool<<<nbPool, 256>>>(batch, ph);
    k_final<<<1, 256>>>(bn_fc_g, bn_fc_b, W_fc, b_fc,
                        bn_hid_g, bn_hid_b, W_cls, b_cls, out);
}

// round 8
// speedup vs baseline: 1.0830x; 1.0033x over previous
#include <cuda_runtime.h>
#include <cuda_bf16.h>
#include <math.h>
#include <stdint.h>

#define NN 100000
#define EE 1200000
#define CC 64
#define HH 64
#define OUTC 10
#define GG 128
#define LL 3
#define EPSBN 1e-5f

// ---------------- scratch (device globals) ----------------
__device__ float g_h [NN * HH];
__device__ float g_aw[NN * HH];
__device__ int   g_outdeg[NN];
__device__ int   g_indeg [NN];
__device__ int   g_rowptr[NN + 1];
__device__ int   g_cur   [NN];
__device__ int   g_col   [EE];
__device__ float g_dis   [NN];
__device__ int   g_bsum  [128];
__device__ int   g_boff  [128];
__device__ float g_stat_s[4 * 64];
__device__ float g_stat_q[4 * 64];
__device__ float g_hg    [GG * HH];
// pre-split transposed weights, packed bf16 k-pairs: [layer][n][kp]
__device__ uint32_t g_Bhi[4 * 2048];
__device__ uint32_t g_Blo[4 * 2048];

// split two floats into packed bf16x2 hi and lo parts
static __device__ __forceinline__ void split2(float x, float y, uint32_t& hi, uint32_t& lo) {
    __nv_bfloat16 hx = __float2bfloat16(x), hy = __float2bfloat16(y);
    __nv_bfloat16 lx = __float2bfloat16(x - __bfloat162float(hx));
    __nv_bfloat16 ly = __float2bfloat16(y - __bfloat162float(hy));
    hi = (uint32_t)__bfloat16_as_ushort(hx) | ((uint32_t)__bfloat16_as_ushort(hy) << 16);
    lo = (uint32_t)__bfloat16_as_ushort(lx) | ((uint32_t)__bfloat16_as_ushort(ly) << 16);
}

#define MMA_BF16(c, a0, a1, a2, a3, b0, b1) \
    asm volatile("mma.sync.aligned.m16n8k16.row.col.f32.bf16.bf16.f32 " \
        "{%0,%1,%2,%3}, {%4,%5,%6,%7}, {%8,%9}, {%0,%1,%2,%3};" \
        : "+f"(c[0]), "+f"(c[1]), "+f"(c[2]), "+f"(c[3]) \
        : "r"(a0), "r"(a1), "r"(a2), "r"(a3), "r"(b0), "r"(b1))

// ---------------- CSR chain ----------------
__global__ void k_zero_deg() {
    int i = blockIdx.x * blockDim.x + threadIdx.x;
    if (i < NN) { g_outdeg[i] = 0; g_indeg[i] = 0; }
}

__global__ void k_hist(const int* __restrict__ src, const int* __restrict__ dst) {
    int e = blockIdx.x * blockDim.x + threadIdx.x;
    if (e < EE) {
        atomicAdd(&g_indeg[dst[e]], 1);
        atomicAdd(&g_outdeg[src[e]], 1);
    }
}

__global__ void k_scan1() {
    __shared__ int sb[1024];
    int t = threadIdx.x;
    int i = blockIdx.x * 1024 + t;
    int v = (i < NN) ? g_indeg[i] : 0;
    sb[t] = v;
    __syncthreads();
    for (int off = 1; off < 1024; off <<= 1) {
        int x = (t >= off) ? sb[t - off] : 0;
        __syncthreads();
        sb[t] += x;
        __syncthreads();
    }
    if (i < NN) g_rowptr[i] = sb[t] - v;
    if (t == 1023) g_bsum[blockIdx.x] = sb[1023];
}

__global__ void k_scan2(int nb) {
    __shared__ int sb[128];
    int t = threadIdx.x;
    int v = (t < nb) ? g_bsum[t] : 0;
    sb[t] = v;
    __syncthreads();
    for (int off = 1; off < 128; off <<= 1) {
        int x = (t >= off) ? sb[t - off] : 0;
        __syncthreads();
        sb[t] += x;
        __syncthreads();
    }
    g_boff[t] = sb[t] - v;
    if (t == 127) g_rowptr[NN] = sb[127];
}

__global__ void k_scan3() {
    int i = blockIdx.x * 1024 + threadIdx.x;
    if (i < NN) {
        int v = g_rowptr[i] + g_boff[blockIdx.x];
        g_rowptr[i] = v;
        g_cur[i] = v;
        g_dis[i] = rsqrtf((float)g_outdeg[i] + 1.0f);
    }
}

__global__ void k_fill(const int* __restrict__ src, const int* __restrict__ dst) {
    int e = blockIdx.x * blockDim.x + threadIdx.x;
    if (e < EE) {
        int d = dst[e];
        int p = atomicAdd(&g_cur[d], 1);
        g_col[p] = src[e];
    }
}

// ---------------- feature chain setup ----------------
__global__ void k_zero_stats() {
    int i = blockIdx.x * blockDim.x + threadIdx.x;
    if (i < 256) { g_stat_s[i] = 0.f; g_stat_q[i] = 0.f; }
    if (i < GG * HH) g_hg[i] = 0.f;
}

// pre-split weights: B[n][kp] = packed (W[2kp][n], W[2kp+1][n]) hi/lo, 4 layers
__global__ void k_prepw(const float* __restrict__ Wf, const float* __restrict__ Wc) {
    int t = blockIdx.x * blockDim.x + threadIdx.x;   // 4*64*32 = 8192
    if (t >= 8192) return;
    int L = t >> 11, rem = t & 2047;
    int n = rem >> 5, kp = rem & 31;
    const float* W = (L == 0) ? Wf : (Wc + (L - 1) * 4096);
    float w0 = W[(2 * kp) * 64 + n];
    float w1 = W[(2 * kp + 1) * 64 + n];
    uint32_t hi, lo;
    split2(w0, w1, hi, lo);
    g_Bhi[L * 2048 + rem] = hi;
    g_Blo[L * 2048 + rem] = lo;
}

__global__ void k_colstats(const float* __restrict__ A) {
    __shared__ float rs[256], rq[256];
    int c  = threadIdx.x & 63;
    int rr = threadIdx.x >> 6;
    int rbeg = blockIdx.x * 512;
    int rend = rbeg + 512; if (rend > NN) rend = NN;
    float s = 0.f, q = 0.f;
    for (int r = rbeg + rr; r < rend; r += 4) {
        float v = A[(size_t)r * 64 + c];
        s += v; q += v * v;
    }
    rs[threadIdx.x] = s; rq[threadIdx.x] = q;
    __syncthreads();
    if (threadIdx.x < 64) {
        float S = rs[threadIdx.x] + rs[threadIdx.x + 64] + rs[threadIdx.x + 128] + rs[threadIdx.x + 192];
        float Q = rq[threadIdx.x] + rq[threadIdx.x + 64] + rq[threadIdx.x + 128] + rq[threadIdx.x + 192];
        atomicAdd(&g_stat_s[threadIdx.x], S);
        atomicAdd(&g_stat_q[threadIdx.x], Q);
    }
}

// ---------------- mma.sync GEMM: out = relu(A'@W + bias), split-bf16, fused stats ----------------
// dyn smem (55808 B): s_s[0,256) s_t[256,512) BH[512,9728) BL[9728,18944)
//                     AH[18944,37376) AL[37376,55808)
//                     T reuse @512 (128x66 f32 = 33792), rS @34304, rQ @35328
__global__ __launch_bounds__(256)
void k_gemm_mma(const float* __restrict__ A, int layer,
                const float* __restrict__ bias, float* __restrict__ out,
                int statSlot, int foldSlot,
                const float* __restrict__ gam, const float* __restrict__ bet) {
    extern __shared__ __align__(16) char sm[];
    float*    s_s = (float*)sm;
    float*    s_t = (float*)(sm + 256);
    uint32_t* BH  = (uint32_t*)(sm + 512);
    uint32_t* BL  = (uint32_t*)(sm + 9728);
    uint32_t* AH  = (uint32_t*)(sm + 18944);
    uint32_t* AL  = (uint32_t*)(sm + 37376);
    int tid = threadIdx.x;
    int rowBase = blockIdx.x * 128;

    if (foldSlot >= 0 && tid < 64) {
        float invn = 1.0f / (float)NN;
        float mu  = g_stat_s[foldSlot * 64 + tid] * invn;
        float var = fmaxf(g_stat_q[foldSlot * 64 + tid] * invn - mu * mu, 0.f);
        float sc = rsqrtf(var + EPSBN) * gam[tid];
        s_s[tid] = sc;
        s_t[tid] = bet[tid] - mu * sc;
    }

    // stage B (stride 36 words per n-row)
    {
        const uint32_t* gBH = g_Bhi + layer * 2048;
        const uint32_t* gBL = g_Blo + layer * 2048;
        for (int i = tid; i < 2048; i += 256) {
            int n = i >> 5, kp = i & 31;
            BH[n * 36 + kp] = gBH[i];
            BL[n * 36 + kp] = gBL[i];
        }
    }
    __syncthreads();   // s_s/s_t visible

    // stage A: thread = (row, half); split/pack/store
    {
        int row = tid >> 1, half = tid & 1;
        int grow = rowBase + row;
        bool valid = grow < NN;
        const float4* ap = (const float4*)(A + (size_t)grow * 64 + half * 32);
        bool dofold = (foldSlot >= 0);
        uint32_t hb[16], lb[16];
        #pragma unroll
        for (int j = 0; j < 8; j++) {
            float4 v = valid ? ap[j] : make_float4(0.f, 0.f, 0.f, 0.f);
            if (dofold) {
                int c0 = half * 32 + j * 4;
                v.x = v.x * s_s[c0]     + s_t[c0];
                v.y = v.y * s_s[c0 + 1] + s_t[c0 + 1];
                v.z = v.z * s_s[c0 + 2] + s_t[c0 + 2];
                v.w = v.w * s_s[c0 + 3] + s_t[c0 + 3];
            }
            split2(v.x, v.y, hb[2 * j],     lb[2 * j]);
            split2(v.z, v.w, hb[2 * j + 1], lb[2 * j + 1]);
        }
        uint32_t base = row * 36 + half * 16;
        #pragma unroll
        for (int j = 0; j < 4; j++) {
            *(uint4*)(AH + base + 4 * j) = make_uint4(hb[4 * j], hb[4 * j + 1], hb[4 * j + 2], hb[4 * j + 3]);
            *(uint4*)(AL + base + 4 * j) = make_uint4(lb[4 * j], lb[4 * j + 1], lb[4 * j + 2], lb[4 * j + 3]);
        }
    }
    __syncthreads();

    // mma main: warp wr owns rows wr*16..+15, all 64 cols
    int lane = tid & 31, wr = tid >> 5;
    int g = lane >> 2, t = lane & 3;
    float acc[8][4];
    #pragma unroll
    for (int nf = 0; nf < 8; nf++)
        #pragma unroll
        for (int j = 0; j < 4; j++) acc[nf][j] = 0.f;

    int ar0 = (wr * 16 + g) * 36;
    int ar1 = (wr * 16 + g + 8) * 36;
    #pragma unroll
    for (int kc = 0; kc < 4; kc++) {
        int kb = kc * 8 + t;
        uint32_t ah0 = AH[ar0 + kb],     ah1 = AH[ar1 + kb];
        uint32_t ah2 = AH[ar0 + kb + 4], ah3 = AH[ar1 + kb + 4];
        uint32_t al0 = AL[ar0 + kb],     al1 = AL[ar1 + kb];
        uint32_t al2 = AL[ar0 + kb + 4], al3 = AL[ar1 + kb + 4];
        #pragma unroll
        for (int nf = 0; nf < 8; nf++) {
            int nb = (nf * 8 + g) * 36 + kb;
            uint32_t bh0 = BH[nb], bh1 = BH[nb + 4];
            uint32_t bl0 = BL[nb], bl1 = BL[nb + 4];
            MMA_BF16(acc[nf], ah0, ah1, ah2, ah3, bh0, bh1);
            MMA_BF16(acc[nf], ah0, ah1, ah2, ah3, bl0, bl1);
            MMA_BF16(acc[nf], al0, al1, al2, al3, bh0, bh1);
        }
    }
    __syncthreads();   // smem reads done; T may overwrite

    // epilogue: bias + relu + store (+ T for stats)
    {
        int r0 = rowBase + wr * 16 + g, r1 = r0 + 8;
        bool v0 = r0 < NN, v1 = r1 < NN;
        float* T = (float*)(sm + 512);
        bool dostat = (statSlot >= 0);
        #pragma unroll
        for (int nf = 0; nf < 8; nf++) {
            int col = nf * 8 + 2 * t;
            float2 bb = *(const float2*)(bias + col);
            float2 o0, o1;
            o0.x = fmaxf(acc[nf][0] + bb.x, 0.f);
            o0.y = fmaxf(acc[nf][1] + bb.y, 0.f);
            o1.x = fmaxf(acc[nf][2] + bb.x, 0.f);
            o1.y = fmaxf(acc[nf][3] + bb.y, 0.f);
            if (v0) *(float2*)(out + (size_t)r0 * 64 + col) = o0;
            if (v1) *(float2*)(out + (size_t)r1 * 64 + col) = o1;
            if (dostat) {
                if (!v0) { o0.x = 0.f; o0.y = 0.f; }
                if (!v1) { o1.x = 0.f; o1.y = 0.f; }
                *(float2*)(T + (wr * 16 + g) * 66 + col)     = o0;
                *(float2*)(T + (wr * 16 + g + 8) * 66 + col) = o1;
            }
        }
    }
    if (statSlot >= 0) {
        __syncthreads();
        float* T  = (float*)(sm + 512);
        float* rS = (float*)(sm + 34304);
        float* rQ = (float*)(sm + 35328);
        int c = tid & 63, q = tid >> 6;
        float S = 0.f, Q = 0.f;
        for (int r = q * 32; r < q * 32 + 32; r++) {
            float v = T[r * 66 + c];
            S += v; Q += v * v;
        }
        rS[tid] = S; rQ[tid] = Q;
        __syncthreads();
        if (tid < 64) {
            atomicAdd(&g_stat_s[statSlot * 64 + tid], rS[tid] + rS[tid + 64] + rS[tid + 128] + rS[tid + 192]);
            atomicAdd(&g_stat_q[statSlot * 64 + tid], rQ[tid] + rQ[tid + 64] + rQ[tid + 128] + rQ[tid + 192]);
        }
    }
}

// ---------------- aggregation (warp per node; proven body) ----------------
__global__ __launch_bounds__(256)
void k_agg(const float* __restrict__ Ain, float* __restrict__ Aout,
           int slot, const float* __restrict__ gam, const float* __restrict__ bet) {
    __shared__ float s_sc[64], s_sh[64];
    if (threadIdx.x < 64) {
        float invn = 1.0f / (float)NN;
        float mu  = g_stat_s[slot * 64 + threadIdx.x] * invn;
        float var = fmaxf(g_stat_q[slot * 64 + threadIdx.x] * invn - mu * mu, 0.f);
        float sc = rsqrtf(var + EPSBN) * gam[threadIdx.x];
        s_sc[threadIdx.x] = sc;
        s_sh[threadIdx.x] = bet[threadIdx.x] - mu * sc;
    }
    __syncthreads();

    int gtid = blockIdx.x * 256 + threadIdx.x;
    int i = gtid >> 5;
    int lane = gtid & 31;
    if (i >= NN) return;
    int c0 = lane * 2;
    float di = g_dis[i];
    int e = g_rowptr[i], end = g_rowptr[i + 1];
    float a0 = 0.f, a1 = 0.f, ws = 0.f;

    for (; e + 4 <= end; e += 4) {
        int s0 = g_col[e], s1 = g_col[e + 1], s2 = g_col[e + 2], s3 = g_col[e + 3];
        float w0 = g_dis[s0], w1 = g_dis[s1], w2 = g_dis[s2], w3 = g_dis[s3];
        float2 v0 = *(const float2*)&Ain[(size_t)s0 * 64 + c0];
        float2 v1 = *(const float2*)&Ain[(size_t)s1 * 64 + c0];
        float2 v2 = *(const float2*)&Ain[(size_t)s2 * 64 + c0];
        float2 v3 = *(const float2*)&Ain[(size_t)s3 * 64 + c0];
        w0 *= di; w1 *= di; w2 *= di; w3 *= di;
        a0 = fmaf(w0, v0.x, a0); a1 = fmaf(w0, v0.y, a1);
        a0 = fmaf(w1, v1.x, a0); a1 = fmaf(w1, v1.y, a1);
        a0 = fmaf(w2, v2.x, a0); a1 = fmaf(w2, v2.y, a1);
        a0 = fmaf(w3, v3.x, a0); a1 = fmaf(w3, v3.y, a1);
        ws += w0 + w1 + w2 + w3;
    }
    for (; e < end; e++) {
        int s = g_col[e];
        float w = di * g_dis[s];
        float2 v = *(const float2*)&Ain[(size_t)s * 64 + c0];
        a0 = fmaf(w, v.x, a0);
        a1 = fmaf(w, v.y, a1);
        ws += w;
    }
    {
        float w = di * di;
        float2 v = *(const float2*)&Ain[(size_t)i * 64 + c0];
        a0 = fmaf(w, v.x, a0);
        a1 = fmaf(w, v.y, a1);
        ws += w;
    }
    float o0 = s_sc[c0]     * a0 + ws * s_sh[c0];
    float o1 = s_sc[c0 + 1] * a1 + ws * s_sh[c0 + 1];
    *(float2*)&Aout[(size_t)i * 64 + c0] = make_float2(o0, o1);
}

// ---------------- pooling ----------------
__global__ void k_pool(const int* __restrict__ batch, const float* __restrict__ hin) {
    int gtid = blockIdx.x * 256 + threadIdx.x;
    int warp = gtid >> 5;
    int lane = gtid & 31;
    int n0 = warp * 16;
    if (n0 >= NN) return;
    int nend = n0 + 16; if (nend > NN) nend = NN;
    int c0 = lane * 2;
    float a0 = 0.f, a1 = 0.f;
    int curg = batch[n0];
    for (int nd = n0; nd < nend; nd++) {
        int g = batch[nd];
        if (g != curg) {
            atomicAdd(&g_hg[curg * 64 + c0],     a0);
            atomicAdd(&g_hg[curg * 64 + c0 + 1], a1);
            a0 = 0.f; a1 = 0.f; curg = g;
        }
        float2 v = *(const float2*)&hin[(size_t)nd * 64 + c0];
        a0 += v.x; a1 += v.y;
    }
    atomicAdd(&g_hg[curg * 64 + c0],     a0);
    atomicAdd(&g_hg[curg * 64 + c0 + 1], a1);
}

// ---------------- final head ----------------
__global__ __launch_bounds__(256, 1)
void k_final(const float* __restrict__ bn1g, const float* __restrict__ bn1b,
             const float* __restrict__ Wfc,  const float* __restrict__ bfc,
             const float* __restrict__ bn2g, const float* __restrict__ bn2b,
             const float* __restrict__ Wcls, const float* __restrict__ bcls,
             float* __restrict__ out) {
    __shared__ float sA[128 * 65];
    __shared__ float red[256], red2[256];
    __shared__ float s_s[64], s_t[64];
    int tid = threadIdx.x;
    int c = tid & 63, rr = tid >> 6;

    for (int i = tid; i < 128 * 64; i += 256)
        sA[(i >> 6) * 65 + (i & 63)] = g_hg[i];
    __syncthreads();

    float s = 0.f, q = 0.f;
    for (int r = rr; r < 128; r += 4) {
        float v = sA[r * 65 + c];
        s += v; q += v * v;
    }
    red[tid] = s; red2[tid] = q;
    __syncthreads();
    if (tid < 64) {
        float S = red [tid] + red [tid + 64] + red [tid + 128] + red [tid + 192];
        float Q = red2[tid] + red2[tid + 64] + red2[tid + 128] + red2[tid + 192];
        float mu = S * (1.f / 128.f);
        float var = fmaxf(Q * (1.f / 128.f) - mu * mu, 0.f);
        float inv = rsqrtf(var + EPSBN);
        float sc = inv * bn1g[tid];
        s_s[tid] = sc;
        s_t[tid] = bn1b[tid] - mu * sc;
    }
    __syncthreads();
    for (int r = rr; r < 128; r += 4)
        sA[r * 65 + c] = sA[r * 65 + c] * s_s[c] + s_t[c];
    __syncthreads();

    float wreg[64];
    #pragma unroll
    for (int k = 0; k < 64; k++) wreg[k] = Wfc[k * 64 + c];
    float acc[32];
    for (int ri = 0; ri < 32; ri++) {
        int r = rr + ri * 4;
        float a = bfc[c];
        #pragma unroll
        for (int k = 0; k < 64; k++) a = fmaf(sA[r * 65 + k], wreg[k], a);
        acc[ri] = fmaxf(a, 0.f);
    }
    __syncthreads();
    for (int ri = 0; ri < 32; ri++) sA[(rr + ri * 4) * 65 + c] = acc[ri];
    __syncthreads();

    s = 0.f; q = 0.f;
    for (int r = rr; r < 128; r += 4) {
        float v = sA[r * 65 + c];
        s += v; q += v * v;
    }
    red[tid] = s; red2[tid] = q;
    __syncthreads();
    if (tid < 64) {
        float S = red [tid] + red [tid + 64] + red [tid + 128] + red [tid + 192];
        float Q = red2[tid] + red2[tid + 64] + red2[tid + 128] + red2[tid + 192];
        float mu = S * (1.f / 128.f);
        float var = fmaxf(Q * (1.f / 128.f) - mu * mu, 0.f);
        float inv = rsqrtf(var + EPSBN);
        float sc = inv * bn2g[tid];
        s_s[tid] = sc;
        s_t[tid] = bn2b[tid] - mu * sc;
    }
    __syncthreads();

    if (tid < 128) {
        int r = tid;
        float logits[10];
        #pragma unroll
        for (int j = 0; j < 10; j++) logits[j] = bcls[j];
        for (int k = 0; k < 64; k++) {
            float v = sA[r * 65 + k] * s_s[k] + s_t[k];
            #pragma unroll
            for (int j = 0; j < 10; j++)
                logits[j] = fmaf(v, Wcls[k * 10 + j], logits[j]);
        }
        float m = logits[0];
        #pragma unroll
        for (int j = 1; j < 10; j++) m = fmaxf(m, logits[j]);
        float se = 0.f;
        #pragma unroll
        for (int j = 0; j < 10; j++) se += expf(logits[j] - m);
        float lse = logf(se) + m;
        #pragma unroll
        for (int j = 0; j < 10; j++) out[r * 10 + j] = logits[j] - lse;
    }
}

// ---------------- host launch ----------------
extern "C" void kernel_launch(void* const* d_in, const int* in_sizes, int n_in,
                              void* d_out, int out_size) {
    const float* x         = (const float*)d_in[0];
    const int*   ei        = (const int*)  d_in[1];
    const int*   batch     = (const int*)  d_in[2];
    const float* bn_feat_g = (const float*)d_in[3];
    const float* bn_feat_b = (const float*)d_in[4];
    const float* W_feat    = (const float*)d_in[5];
    const float* b_feat    = (const float*)d_in[6];
    const float* conv_bn_g = (const float*)d_in[7];
    const float* conv_bn_b = (const float*)d_in[8];
    const float* conv_W    = (const float*)d_in[9];
    const float* conv_b    = (const float*)d_in[10];
    const float* bn_fc_g   = (const float*)d_in[11];
    const float* bn_fc_b   = (const float*)d_in[12];
    const float* W_fc      = (const float*)d_in[13];
    const float* b_fc      = (const float*)d_in[14];
    const float* bn_hid_g  = (const float*)d_in[15];
    const float* bn_hid_b  = (const float*)d_in[16];
    const float* W_cls     = (const float*)d_in[17];
    const float* b_cls     = (const float*)d_in[18];
    float* out = (float*)d_out;

    void *ph_v, *paw_v;
    cudaGetSymbolAddress(&ph_v,  g_h);
    cudaGetSymbolAddress(&paw_v, g_aw);
    float* ph  = (float*)ph_v;
    float* paw = (float*)paw_v;

    const int* src = ei;
    const int* dst = ei + EE;

    const int nbScan = (NN + 1023) / 1024;
    const int nbNode = (NN + 255) / 256;
    const int nbEdge = (EE + 255) / 256;
    const int nbStat = (NN + 511) / 512;
    const int nbGemm = (NN + 127) / 128;   // 782
    const int nbAgg  = (NN * 32 + 255) / 256;
    const int nbPool = (((NN + 15) / 16) * 32 + 255) / 256;
    const int MMA_SMEM = 55808;

    static cudaStream_t s_csr = 0;
    static cudaEvent_t  ev_fork = 0, ev_join = 0;
    static bool attrset = false;
    if (!s_csr) {
        cudaStreamCreateWithFlags(&s_csr, cudaStreamNonBlocking);
        cudaEventCreateWithFlags(&ev_fork, cudaEventDisableTiming);
        cudaEventCreateWithFlags(&ev_join, cudaEventDisableTiming);
    }
    if (!attrset) {
        cudaFuncSetAttribute(k_gemm_mma, cudaFuncAttributeMaxDynamicSharedMemorySize, MMA_SMEM);
        attrset = true;
    }

    // ---- fork: CSR chain on s_csr, feature chain on stream 0 ----
    cudaEventRecord(ev_fork, 0);
    cudaStreamWaitEvent(s_csr, ev_fork, 0);

    k_zero_deg<<<nbNode, 256, 0, s_csr>>>();
    k_hist<<<nbEdge, 256, 0, s_csr>>>(src, dst);
    k_scan1<<<nbScan, 1024, 0, s_csr>>>();
    k_scan2<<<1, 128, 0, s_csr>>>(nbScan);
    k_scan3<<<nbScan, 1024, 0, s_csr>>>();
    k_fill<<<nbEdge, 256, 0, s_csr>>>(src, dst);
    cudaEventRecord(ev_join, s_csr);

    // feature chain (stream 0)
    k_prepw<<<32, 256>>>(W_feat, conv_W);
    k_zero_stats<<<33, 256>>>();
    k_colstats<<<nbStat, 256>>>(x);
    k_gemm_mma<<<nbGemm, 256, MMA_SMEM>>>(x, 0, b_feat, ph, 1, 0, bn_feat_g, bn_feat_b);

    // ---- join before first aggregation ----
    cudaStreamWaitEvent(0, ev_join, 0);

    // ---- conv layers ----
    for (int l = 0; l < LL; l++) {
        k_agg<<<nbAgg, 256>>>(ph, paw, l + 1, conv_bn_g + l * HH, conv_bn_b + l * HH);
        k_gemm_mma<<<nbGemm, 256, MMA_SMEM>>>(paw, l + 1, conv_b + l * HH, ph,
                                              (l < LL - 1) ? (l + 2) : -1, -1,
                                              (const float*)0, (const float*)0);
    }

    // ---- pool + head ----
    k_pool<<<nbPool, 256>>>(batch, ph);
    k_final<<<1, 256>>>(bn_fc_g, bn_fc_b, W_fc, b_fc,
                        bn_hid_g, bn_hid_b, W_cls, b_cls, out);
}